// round 5
// baseline (speedup 1.0000x reference)
#include <cuda_runtime.h>
#include <math.h>
#include <stdint.h>

#define MROWS 65536          // 4*128*128
#define CIN   180
#define CC2   360
#define NDTOT 3932160        // N*D, identical for all 3 paths (4*128*128*60)

typedef unsigned long long ull;
union F2U { ull u; float2 f; };

// ---------------- scratch (static device globals; no runtime allocation) ----
__device__ float g_X1[(size_t)MROWS * CC2];     // conv1 output (94 MB)
__device__ float g_Q[NDTOT];
__device__ float g_V[NDTOT];
__device__ float g_Yw[NDTOT];
__device__ float g_Ycat[(size_t)MROWS * CIN];   // 47 MB
__device__ float g_part[4194304];               // split-K partials (16 MB)
__device__ float g_psum[256 * CC2];
__device__ float g_psq[256 * CC2];
__device__ float g_scale[CC2];
__device__ float g_shift[CC2];

#define FFMA2(acc, a, b) \
    asm("fma.rn.f32x2 %0, %1, %2, %0;" : "+l"(acc) : "l"(a), "l"(b))

// ====================== GEMM NN: C[M,N] = A[M,K]*B[K,N] (+bias[n]) ==========
// 128x128 tile, BK=8, 256 threads, 8x8 microtile computed as 8x4 f32x2 pairs.
// A tile stored DUPLICATED in smem so (a,a) pairs load directly via LDS.128.
__global__ __launch_bounds__(256, 2) void gemm_nn(
    const float* __restrict__ A, const float* __restrict__ B,
    float* __restrict__ C, int M, int N, int K, const float* __restrict__ bias)
{
    __shared__ float As2[8][256];  // duplicated: As2[k][2m]=As2[k][2m+1]=A[row0+m][kk+k]
    __shared__ float Bs[8][128];
    const int tid  = threadIdx.x;
    const int row0 = blockIdx.y * 128;
    const int col0 = blockIdx.x * 128;
    const int lm   = tid >> 1;          // 0..127
    const int lk4  = (tid & 1) * 4;     // 0 or 4
    const int bk   = tid >> 5;          // 0..7
    const int bn4  = (tid & 31) * 4;    // 0..124
    const int ty   = tid >> 4, tx = tid & 15;

    ull acc[8][4];
#pragma unroll
    for (int i = 0; i < 8; i++)
#pragma unroll
        for (int j = 0; j < 4; j++) acc[i][j] = 0ull;

    const float* Arow = A + (size_t)(row0 + lm) * K;

    // ---- tile loaders (guarded) ----
    float4 av, bv;
    {
        int ka = lk4;
        if (ka + 3 < K) av = *reinterpret_cast<const float4*>(Arow + ka);
        else {
            av = make_float4((ka + 0 < K) ? Arow[ka + 0] : 0.f,
                             (ka + 1 < K) ? Arow[ka + 1] : 0.f,
                             (ka + 2 < K) ? Arow[ka + 2] : 0.f,
                             (ka + 3 < K) ? Arow[ka + 3] : 0.f);
        }
        bv = make_float4(0.f, 0.f, 0.f, 0.f);
        int kb = bk, cb = col0 + bn4;
        if (kb < K) {
            if (cb + 3 < N) bv = *reinterpret_cast<const float4*>(B + (size_t)kb * N + cb);
            else {
                const float* Bp = B + (size_t)kb * N;
                if (cb + 0 < N) bv.x = Bp[cb + 0];
                if (cb + 1 < N) bv.y = Bp[cb + 1];
                if (cb + 2 < N) bv.z = Bp[cb + 2];
                if (cb + 3 < N) bv.w = Bp[cb + 3];
            }
        }
    }

    for (int kk = 0; kk < K; kk += 8) {
        // store current regs to smem (A duplicated)
        *reinterpret_cast<float2*>(&As2[lk4 + 0][2 * lm]) = make_float2(av.x, av.x);
        *reinterpret_cast<float2*>(&As2[lk4 + 1][2 * lm]) = make_float2(av.y, av.y);
        *reinterpret_cast<float2*>(&As2[lk4 + 2][2 * lm]) = make_float2(av.z, av.z);
        *reinterpret_cast<float2*>(&As2[lk4 + 3][2 * lm]) = make_float2(av.w, av.w);
        *reinterpret_cast<float4*>(&Bs[bk][bn4]) = bv;
        __syncthreads();

        // prefetch next tile into registers (overlaps FMA loop)
        if (kk + 8 < K) {
            int ka = kk + 8 + lk4;
            if (ka + 3 < K) av = *reinterpret_cast<const float4*>(Arow + ka);
            else {
                av = make_float4((ka + 0 < K) ? Arow[ka + 0] : 0.f,
                                 (ka + 1 < K) ? Arow[ka + 1] : 0.f,
                                 (ka + 2 < K) ? Arow[ka + 2] : 0.f,
                                 (ka + 3 < K) ? Arow[ka + 3] : 0.f);
            }
            bv = make_float4(0.f, 0.f, 0.f, 0.f);
            int kb = kk + 8 + bk, cb = col0 + bn4;
            if (kb < K) {
                if (cb + 3 < N) bv = *reinterpret_cast<const float4*>(B + (size_t)kb * N + cb);
                else {
                    const float* Bp = B + (size_t)kb * N;
                    if (cb + 0 < N) bv.x = Bp[cb + 0];
                    if (cb + 1 < N) bv.y = Bp[cb + 1];
                    if (cb + 2 < N) bv.z = Bp[cb + 2];
                    if (cb + 3 < N) bv.w = Bp[cb + 3];
                }
            }
        }

#pragma unroll
        for (int k = 0; k < 8; k++) {
            ull a2[8], b2[4];
            ulonglong2 t;
            t = *reinterpret_cast<const ulonglong2*>(&As2[k][ty * 16 + 0]);  a2[0] = t.x; a2[1] = t.y;
            t = *reinterpret_cast<const ulonglong2*>(&As2[k][ty * 16 + 4]);  a2[2] = t.x; a2[3] = t.y;
            t = *reinterpret_cast<const ulonglong2*>(&As2[k][ty * 16 + 8]);  a2[4] = t.x; a2[5] = t.y;
            t = *reinterpret_cast<const ulonglong2*>(&As2[k][ty * 16 + 12]); a2[6] = t.x; a2[7] = t.y;
            t = *reinterpret_cast<const ulonglong2*>(&Bs[k][tx * 8]);        b2[0] = t.x; b2[1] = t.y;
            t = *reinterpret_cast<const ulonglong2*>(&Bs[k][tx * 8 + 4]);    b2[2] = t.x; b2[3] = t.y;
#pragma unroll
            for (int i = 0; i < 8; i++) {
                FFMA2(acc[i][0], a2[i], b2[0]);
                FFMA2(acc[i][1], a2[i], b2[1]);
                FFMA2(acc[i][2], a2[i], b2[2]);
                FFMA2(acc[i][3], a2[i], b2[3]);
            }
        }
        __syncthreads();
    }

    const int crow = row0 + ty * 8;
    const int ccol = col0 + tx * 8;
    float bb[8];
#pragma unroll
    for (int j = 0; j < 8; j++)
        bb[j] = (bias != nullptr && ccol + j < N) ? bias[ccol + j] : 0.f;

    if (col0 + 128 <= N) {
#pragma unroll
        for (int i = 0; i < 8; i++) {
            float* Cp = C + (size_t)(crow + i) * N + ccol;
            F2U p0, p1, p2, p3;
            p0.u = acc[i][0]; p1.u = acc[i][1]; p2.u = acc[i][2]; p3.u = acc[i][3];
            float4 o0 = make_float4(p0.f.x + bb[0], p0.f.y + bb[1], p1.f.x + bb[2], p1.f.y + bb[3]);
            float4 o1 = make_float4(p2.f.x + bb[4], p2.f.y + bb[5], p3.f.x + bb[6], p3.f.y + bb[7]);
            *reinterpret_cast<float4*>(Cp)     = o0;
            *reinterpret_cast<float4*>(Cp + 4) = o1;
        }
    } else {
#pragma unroll
        for (int i = 0; i < 8; i++) {
            float vals[8];
            F2U p;
#pragma unroll
            for (int j = 0; j < 4; j++) { p.u = acc[i][j]; vals[2 * j] = p.f.x; vals[2 * j + 1] = p.f.y; }
#pragma unroll
            for (int j = 0; j < 8; j++)
                if (ccol + j < N)
                    C[(size_t)(crow + i) * N + ccol + j] = vals[j] + bb[j];
        }
    }
}

// ====================== GEMM NT: C[M,N] = A[M,K]*B[N,K]^T, optional split-K ==
__global__ __launch_bounds__(256, 2) void gemm_nt(
    const float* __restrict__ A, const float* __restrict__ B,
    float* __restrict__ C, int M, int N, int K, int Kc)
{
    __shared__ float As2[8][256];  // duplicated A pairs
    __shared__ float Bs[8][132];
    const int tid  = threadIdx.x;
    const int row0 = blockIdx.y * 128;
    const int col0 = blockIdx.x * 128;
    const int zi   = blockIdx.z;
    const int kbase = zi * Kc;
    int kend = kbase + Kc; if (kend > K) kend = K;
    if (gridDim.z > 1) C += (size_t)zi * M * N;

    const int lm  = tid >> 1;
    const int lk4 = (tid & 1) * 4;
    const int ty  = tid >> 4, tx = tid & 15;

    ull acc[8][4];
#pragma unroll
    for (int i = 0; i < 8; i++)
#pragma unroll
        for (int j = 0; j < 4; j++) acc[i][j] = 0ull;

    const float* Arow = A + (size_t)(row0 + lm) * K;
    const float* Brow = B + (size_t)(col0 + lm) * K;

    float4 av, bv;
    {
        int ka = kbase + lk4;
        if (ka + 3 < kend) {
            av = *reinterpret_cast<const float4*>(Arow + ka);
            bv = *reinterpret_cast<const float4*>(Brow + ka);
        } else {
            float ta[4] = {0,0,0,0}, tb[4] = {0,0,0,0};
#pragma unroll
            for (int j = 0; j < 4; j++)
                if (ka + j < kend) { ta[j] = Arow[ka + j]; tb[j] = Brow[ka + j]; }
            av = make_float4(ta[0], ta[1], ta[2], ta[3]);
            bv = make_float4(tb[0], tb[1], tb[2], tb[3]);
        }
    }

    for (int kk = kbase; kk < kend; kk += 8) {
        *reinterpret_cast<float2*>(&As2[lk4 + 0][2 * lm]) = make_float2(av.x, av.x);
        *reinterpret_cast<float2*>(&As2[lk4 + 1][2 * lm]) = make_float2(av.y, av.y);
        *reinterpret_cast<float2*>(&As2[lk4 + 2][2 * lm]) = make_float2(av.z, av.z);
        *reinterpret_cast<float2*>(&As2[lk4 + 3][2 * lm]) = make_float2(av.w, av.w);
        Bs[lk4 + 0][lm] = bv.x; Bs[lk4 + 1][lm] = bv.y;
        Bs[lk4 + 2][lm] = bv.z; Bs[lk4 + 3][lm] = bv.w;
        __syncthreads();

        if (kk + 8 < kend) {
            int ka = kk + 8 + lk4;
            if (ka + 3 < kend) {
                av = *reinterpret_cast<const float4*>(Arow + ka);
                bv = *reinterpret_cast<const float4*>(Brow + ka);
            } else {
                float ta[4] = {0,0,0,0}, tb[4] = {0,0,0,0};
#pragma unroll
                for (int j = 0; j < 4; j++)
                    if (ka + j < kend) { ta[j] = Arow[ka + j]; tb[j] = Brow[ka + j]; }
                av = make_float4(ta[0], ta[1], ta[2], ta[3]);
                bv = make_float4(tb[0], tb[1], tb[2], tb[3]);
            }
        }

#pragma unroll
        for (int k = 0; k < 8; k++) {
            ull a2[8], b2[4];
            ulonglong2 t;
            t = *reinterpret_cast<const ulonglong2*>(&As2[k][ty * 16 + 0]);  a2[0] = t.x; a2[1] = t.y;
            t = *reinterpret_cast<const ulonglong2*>(&As2[k][ty * 16 + 4]);  a2[2] = t.x; a2[3] = t.y;
            t = *reinterpret_cast<const ulonglong2*>(&As2[k][ty * 16 + 8]);  a2[4] = t.x; a2[5] = t.y;
            t = *reinterpret_cast<const ulonglong2*>(&As2[k][ty * 16 + 12]); a2[6] = t.x; a2[7] = t.y;
            t = *reinterpret_cast<const ulonglong2*>(&Bs[k][tx * 8]);        b2[0] = t.x; b2[1] = t.y;
            t = *reinterpret_cast<const ulonglong2*>(&Bs[k][tx * 8 + 4]);    b2[2] = t.x; b2[3] = t.y;
#pragma unroll
            for (int i = 0; i < 8; i++) {
                FFMA2(acc[i][0], a2[i], b2[0]);
                FFMA2(acc[i][1], a2[i], b2[1]);
                FFMA2(acc[i][2], a2[i], b2[2]);
                FFMA2(acc[i][3], a2[i], b2[3]);
            }
        }
        __syncthreads();
    }

    const int crow = row0 + ty * 8;
    const int ccol = col0 + tx * 8;
#pragma unroll
    for (int i = 0; i < 8; i++) {
        float* Cp = C + (size_t)(crow + i) * N + ccol;
        F2U p0, p1, p2, p3;
        p0.u = acc[i][0]; p1.u = acc[i][1]; p2.u = acc[i][2]; p3.u = acc[i][3];
        float4 o0 = make_float4(p0.f.x, p0.f.y, p1.f.x, p1.f.y);
        float4 o1 = make_float4(p2.f.x, p2.f.y, p3.f.x, p3.f.y);
        *reinterpret_cast<float4*>(Cp)     = o0;
        *reinterpret_cast<float4*>(Cp + 4) = o1;
    }
}

// ====================== split-K reduce =======================================
__global__ void reduce_k(const float* __restrict__ part, float* __restrict__ dst,
                         int z, size_t len)
{
    size_t i = (size_t)blockIdx.x * 256 + threadIdx.x;
    if (i >= len) return;
    float s = 0.f;
    for (int zz = 0; zz < z; zz++) s += part[(size_t)zz * len + i];
    dst[i] = s;
}

// ====================== BatchNorm statistics (deterministic, 2-stage) ========
__global__ void bn_partial(const float* __restrict__ X1,
                           float* __restrict__ psum, float* __restrict__ psq)
{
    int ch = threadIdx.x;
    if (ch >= CC2) return;
    int b = blockIdx.x;
    const float* base = X1 + (size_t)b * 256 * CC2 + ch;
    float s = 0.f, q = 0.f;
    for (int r = 0; r < 256; r++) {
        float v = base[(size_t)r * CC2];
        s += v; q += v * v;
    }
    psum[b * CC2 + ch] = s;
    psq[b * CC2 + ch]  = q;
}

__global__ void bn_final(const float* __restrict__ psum, const float* __restrict__ psq,
                         const float* __restrict__ bns, const float* __restrict__ bnb,
                         float* __restrict__ scl, float* __restrict__ shf)
{
    int ch = threadIdx.x;
    if (ch >= CC2) return;
    float s = 0.f, q = 0.f;
    for (int b = 0; b < 256; b++) { s += psum[b * CC2 + ch]; q += psq[b * CC2 + ch]; }
    float mean = s * (1.f / MROWS);
    float var  = q * (1.f / MROWS) - mean * mean;
    float sc = bns[ch] / sqrtf(var + 1e-5f);
    scl[ch] = sc;
    shf[ch] = bnb[ch] - mean * sc;
}

// ====================== window gather (with roll -ws/2) + fused BN ===========
__global__ void gather_qv(const float* __restrict__ X1,
                          const float* __restrict__ scl, const float* __restrict__ shf,
                          float* __restrict__ Q, float* __restrict__ V,
                          int gbase, int lws, int total)
{
    int idx = blockIdx.x * 256 + threadIdx.x;
    if (idx >= total) return;
    const int ws = 1 << lws;
    const int sh = ws >> 1;
    const int D  = (ws * ws) * 60;
    int n = idx / D;
    int d = idx - n * D;
    int cc = d % 60;
    int t  = d / 60;
    int dw = t & (ws - 1);
    int dh = t >> lws;
    const int lh = 7 - lws;
    int b   = n >> (2 * lh);
    int rem = n & ((1 << (2 * lh)) - 1);
    int hh  = rem >> lh;
    int ww  = rem & ((1 << lh) - 1);
    int r = ((hh << lws) + dh + sh) & 127;
    int s = ((ww << lws) + dw + sh) & 127;
    size_t m = ((size_t)b << 14) + ((size_t)r << 7) + s;
    size_t base = m * CC2 + gbase + cc;
    int chq = gbase + cc, chv = chq + 60;
    Q[idx] = X1[base]      * scl[chq] + shf[chq];
    V[idx] = X1[base + 60] * scl[chv] + shf[chv];
}

// ====================== window scatter (inverse roll +ws/2) ==================
__global__ void scatter_y(const float* __restrict__ Yw, float* __restrict__ Ycat,
                          int g, int lws)
{
    int idx = blockIdx.x * 256 + threadIdx.x;
    if (idx >= MROWS * 60) return;
    int cc = idx % 60;
    int m  = idx / 60;
    int so = m & 127, ro = (m >> 7) & 127, b = m >> 14;
    const int ws = 1 << lws, sh = ws >> 1, lh = 7 - lws;
    int r = (ro - sh) & 127, s = (so - sh) & 127;
    int hh = r >> lws, dh = r & (ws - 1);
    int ww = s >> lws, dw = s & (ws - 1);
    int n = (((b << lh) + hh) << lh) + ww;
    int D = (ws * ws) * 60;
    int d = ((dh << lws) + dw) * 60 + cc;
    Ycat[(size_t)m * CIN + g * 60 + cc] = Yw[(size_t)n * D + d];
}

// ====================== in-place row softmax =================================
__global__ __launch_bounds__(256) void softmax_rows(float* __restrict__ data, int N)
{
    __shared__ float sb[4096];
    __shared__ float red[40];
    const int tid = threadIdx.x;
    float* p = data + (size_t)blockIdx.x * N;

    float mx = -3.402823466e+38f;
    for (int i = tid; i < N; i += 256) { float v = p[i]; sb[i] = v; mx = fmaxf(mx, v); }
#pragma unroll
    for (int o = 16; o > 0; o >>= 1) mx = fmaxf(mx, __shfl_xor_sync(0xffffffffu, mx, o));
    if ((tid & 31) == 0) red[tid >> 5] = mx;
    __syncthreads();
    if (tid == 0) {
        float m2 = red[0];
        for (int i = 1; i < 8; i++) m2 = fmaxf(m2, red[i]);
        red[32] = m2;
    }
    __syncthreads();
    const float mAll = red[32];

    float sum = 0.f;
    for (int i = tid; i < N; i += 256) { float e = expf(sb[i] - mAll); sb[i] = e; sum += e; }
#pragma unroll
    for (int o = 16; o > 0; o >>= 1) sum += __shfl_xor_sync(0xffffffffu, sum, o);
    __syncthreads();
    if ((tid & 31) == 0) red[tid >> 5] = sum;
    __syncthreads();
    if (tid == 0) {
        float s2 = 0.f;
        for (int i = 0; i < 8; i++) s2 += red[i];
        red[33] = 1.f / s2;
    }
    __syncthreads();
    const float inv = red[33];
    for (int i = tid; i < N; i += 256) p[i] = sb[i] * inv;
}

// ====================== host orchestration ===================================
extern "C" void kernel_launch(void* const* d_in, const int* in_sizes, int n_in,
                              void* d_out, int out_size)
{
    const float* in  = (const float*)d_in[0];
    const float* w1  = (const float*)d_in[1];
    const float* b1  = (const float*)d_in[2];
    const float* bns = (const float*)d_in[3];
    const float* bnb = (const float*)d_in[4];
    const float* w2  = (const float*)d_in[5];
    const float* b2  = (const float*)d_in[6];
    float* out = (float*)d_out;

    float *X1, *Q, *V, *Yw, *Yc, *part, *psum, *psq, *scl, *shf;
    cudaGetSymbolAddress((void**)&X1,   g_X1);
    cudaGetSymbolAddress((void**)&Q,    g_Q);
    cudaGetSymbolAddress((void**)&V,    g_V);
    cudaGetSymbolAddress((void**)&Yw,   g_Yw);
    cudaGetSymbolAddress((void**)&Yc,   g_Ycat);
    cudaGetSymbolAddress((void**)&part, g_part);
    cudaGetSymbolAddress((void**)&psum, g_psum);
    cudaGetSymbolAddress((void**)&psq,  g_psq);
    cudaGetSymbolAddress((void**)&scl,  g_scale);
    cudaGetSymbolAddress((void**)&shf,  g_shift);

    // 1) conv1: X1 = in @ W1 + b1   (65536 x 360, K=180)
    gemm_nn<<<dim3((CC2 + 127) / 128, MROWS / 128), 256>>>(in, w1, X1, MROWS, CC2, CIN, b1);

    // 2) BatchNorm statistics (deterministic two-stage reduction)
    bn_partial<<<256, 384>>>(X1, psum, psq);
    bn_final<<<1, 384>>>(psum, psq, bns, bnb, scl, shf);

    // attention output regions inside d_out: [y | a4 | a8 | a16]
    float* attn[3] = { out + 11796480, out + 28573696, out + 29622272 };
    const int wsv[3]  = {4, 8, 16};
    const int lwsv[3] = {2, 3, 4};

    for (int g = 0; g < 3; g++) {
        const int ws  = wsv[g];
        const int lws = lwsv[g];
        const int Nw  = 4 * (128 / ws) * (128 / ws);   // 4096 / 1024 / 256
        const int D   = ws * ws * 60;                   // 960 / 3840 / 15360

        gather_qv<<<(NDTOT + 255) / 256, 256>>>(X1, scl, shf, Q, V, g * 120, lws, NDTOT);

        if (g == 0) {
            gemm_nt<<<dim3(32, 32, 1), 256>>>(Q, Q, attn[0], 4096, 4096, 960, 960);
        } else if (g == 1) {
            gemm_nt<<<dim3(8, 8, 4), 256>>>(Q, Q, part, 1024, 1024, 3840, 960);
            reduce_k<<<4096, 256>>>(part, attn[1], 4, (size_t)1024 * 1024);
        } else {
            gemm_nt<<<dim3(2, 2, 60), 256>>>(Q, Q, part, 256, 256, 15360, 256);
            reduce_k<<<256, 256>>>(part, attn[2], 60, (size_t)256 * 256);
        }

        softmax_rows<<<Nw, 256>>>(attn[g], Nw);

        gemm_nn<<<dim3((D + 127) / 128, Nw / 128), 256>>>(attn[g], V, Yw, Nw, D, Nw, nullptr);

        scatter_y<<<(MROWS * 60 + 255) / 256, 256>>>(Yw, Yc, g, lws);
    }

    // 8) conv2: y = Ycat @ W2 + b2  -> front of d_out
    gemm_nn<<<dim3((CIN + 127) / 128, MROWS / 128), 256>>>(Yc, w2, out, MROWS, CIN, CIN, b2);
}

// round 7
// speedup vs baseline: 1.1634x; 1.1634x over previous
#include <cuda_runtime.h>
#include <math.h>
#include <stdint.h>

#define MROWS 65536          // 4*128*128
#define CIN   180
#define CC2   360
#define NDTOT 3932160        // N*D for every path (4*128*128*60)
#define PADA  20             // pitch for [row][k16] tiles (A, B-NT)
#define PADB  136            // pitch for [k][n128] tiles (B-NN)

// ---------------- scratch (static device globals; no runtime allocation) ----
__device__ float g_X1[(size_t)MROWS * CC2];      // conv1 output fp32
__device__ float g_inh[(size_t)MROWS * CIN];     // input split
__device__ float g_inl[(size_t)MROWS * CIN];
__device__ float g_w1h[CIN * CC2], g_w1l[CIN * CC2];
__device__ float g_w2h[CIN * CIN], g_w2l[CIN * CIN];
__device__ float g_Qh[NDTOT], g_Ql[NDTOT];
__device__ float g_Vh[NDTOT], g_Vl[NDTOT];
__device__ float g_Yw[NDTOT];
__device__ float g_Ych[(size_t)MROWS * CIN];     // Ycat split
__device__ float g_Ycl[(size_t)MROWS * CIN];
__device__ float g_ah[(size_t)4096 * 4096];      // attn split (max path)
__device__ float g_al[(size_t)4096 * 4096];
__device__ float g_part[4194304];                // split-K partials
__device__ float g_psum[256 * CC2];
__device__ float g_psq[256 * CC2];
__device__ float g_scale[CC2];
__device__ float g_shift[CC2];

// ---------------- helpers ----------------------------------------------------
__device__ __forceinline__ void split2(float x, float& h, float& l) {
    unsigned uh, ul;
    asm("cvt.rna.tf32.f32 %0, %1;" : "=r"(uh) : "f"(x));
    h = __uint_as_float(uh);
    float r = x - h;
    asm("cvt.rna.tf32.f32 %0, %1;" : "=r"(ul) : "f"(r));
    l = __uint_as_float(ul);
}

__device__ __forceinline__ float4 ld4g(const float* p, int i0, int lim) {
    if (i0 + 3 < lim) return *reinterpret_cast<const float4*>(p + i0);
    float4 v = make_float4(0.f, 0.f, 0.f, 0.f);
    if (i0 + 0 < lim) v.x = p[i0 + 0];
    if (i0 + 1 < lim) v.y = p[i0 + 1];
    if (i0 + 2 < lim) v.z = p[i0 + 2];
    if (i0 + 3 < lim) v.w = p[i0 + 3];
    return v;
}

__device__ __forceinline__ void mma_tf32(float* d, const unsigned* a,
                                         const unsigned* b) {
    asm volatile(
        "mma.sync.aligned.m16n8k8.row.col.f32.tf32.tf32.f32 "
        "{%0,%1,%2,%3}, {%4,%5,%6,%7}, {%8,%9}, {%0,%1,%2,%3};"
        : "+f"(d[0]), "+f"(d[1]), "+f"(d[2]), "+f"(d[3])
        : "r"(a[0]), "r"(a[1]), "r"(a[2]), "r"(a[3]), "r"(b[0]), "r"(b[1]));
}

// ============ tensor GEMM (3xTF32): C[M,N] = A[M,K] * B + bias ==============
// BNT=true : B given as [N][K] (NT);  BNT=false : B given as [K][N] (NN).
// CTA tile 128x128, BK=16, 8 warps (each 32x64). Split-K via blockIdx.z/Kc.
// M must be a multiple of 128; N,K arbitrary (guarded).
template <bool BNT>
__global__ __launch_bounds__(256) void gemm_tc(
    const float* __restrict__ Ah, const float* __restrict__ Al,
    const float* __restrict__ Bh, const float* __restrict__ Bl,
    float* __restrict__ C, int M, int N, int K, int Kc,
    const float* __restrict__ bias)
{
    __shared__ float Ah_s[128 * PADA];
    __shared__ float Al_s[128 * PADA];
    __shared__ float Bh_s[2560];           // max(128*PADA=2560, 16*PADB=2176)
    __shared__ float Bl_s[2560];

    const int tid  = threadIdx.x;
    const int row0 = blockIdx.y * 128;
    const int col0 = blockIdx.x * 128;
    const int kbase = blockIdx.z * Kc;
    int kend = kbase + Kc; if (kend > K) kend = K;
    if (gridDim.z > 1) C += (size_t)blockIdx.z * M * N;

    const int wid  = tid >> 5, lane = tid & 31;
    const int wm   = (wid & 3) * 32;       // warp row offset in tile
    const int wn   = (wid >> 2) * 64;      // warp col offset in tile
    const int g    = lane >> 2;            // 0..7
    const int tg   = lane & 3;             // 0..3

    float acc[2][8][4];
#pragma unroll
    for (int mt = 0; mt < 2; mt++)
#pragma unroll
        for (int nt = 0; nt < 8; nt++)
#pragma unroll
            for (int j = 0; j < 4; j++) acc[mt][nt][j] = 0.f;

    // loader thread mapping
    const int lm  = tid >> 1;              // 0..127 (row for A / B-NT)
    const int lkq = (tid & 1) * 8;         // k quad base
    const int bk  = tid >> 4;              // 0..15 (k row for B-NN)
    const int bnq = (tid & 15) * 8;        // n quad base for B-NN

    const float* Arh = Ah + (size_t)(row0 + lm) * K;
    const float* Arl = Al + (size_t)(row0 + lm) * K;
    const float* Brh = BNT ? (Bh + (size_t)(col0 + lm) * K) : Bh;
    const float* Brl = BNT ? (Bl + (size_t)(col0 + lm) * K) : Bl;

    float4 pah0, pah1, pal0, pal1, pbh0, pbh1, pbl0, pbl1;

#define LOAD_STAGE(KK)                                                        \
    do {                                                                      \
        pah0 = ld4g(Arh, (KK) + lkq,     kend);                               \
        pah1 = ld4g(Arh, (KK) + lkq + 4, kend);                               \
        pal0 = ld4g(Arl, (KK) + lkq,     kend);                               \
        pal1 = ld4g(Arl, (KK) + lkq + 4, kend);                               \
        if (BNT) {                                                            \
            pbh0 = ld4g(Brh, (KK) + lkq,     kend);                           \
            pbh1 = ld4g(Brh, (KK) + lkq + 4, kend);                           \
            pbl0 = ld4g(Brl, (KK) + lkq,     kend);                           \
            pbl1 = ld4g(Brl, (KK) + lkq + 4, kend);                           \
        } else {                                                              \
            int kr = (KK) + bk;                                               \
            if (kr < kend) {                                                  \
                const float* bh = Bh + (size_t)kr * N;                        \
                const float* bl = Bl + (size_t)kr * N;                        \
                pbh0 = ld4g(bh, col0 + bnq,     N);                           \
                pbh1 = ld4g(bh, col0 + bnq + 4, N);                           \
                pbl0 = ld4g(bl, col0 + bnq,     N);                           \
                pbl1 = ld4g(bl, col0 + bnq + 4, N);                           \
            } else {                                                          \
                pbh0 = pbh1 = pbl0 = pbl1 = make_float4(0.f, 0.f, 0.f, 0.f);  \
            }                                                                 \
        }                                                                     \
    } while (0)

    LOAD_STAGE(kbase);

    for (int kk = kbase; kk < kend; kk += 16) {
        // stage -> smem
        {
            int ab = lm * PADA + lkq;
            *reinterpret_cast<float4*>(&Ah_s[ab])     = pah0;
            *reinterpret_cast<float4*>(&Ah_s[ab + 4]) = pah1;
            *reinterpret_cast<float4*>(&Al_s[ab])     = pal0;
            *reinterpret_cast<float4*>(&Al_s[ab + 4]) = pal1;
            int bb = BNT ? (lm * PADA + lkq) : (bk * PADB + bnq);
            *reinterpret_cast<float4*>(&Bh_s[bb])     = pbh0;
            *reinterpret_cast<float4*>(&Bh_s[bb + 4]) = pbh1;
            *reinterpret_cast<float4*>(&Bl_s[bb])     = pbl0;
            *reinterpret_cast<float4*>(&Bl_s[bb + 4]) = pbl1;
        }
        __syncthreads();

        if (kk + 16 < kend) LOAD_STAGE(kk + 16);

#pragma unroll
        for (int kh = 0; kh < 2; kh++) {
            const int ko = kh * 8;
            unsigned afh[2][4], afl[2][4];
#pragma unroll
            for (int mt = 0; mt < 2; mt++) {
                int r0 = wm + mt * 16 + g;
                afh[mt][0] = __float_as_uint(Ah_s[r0 * PADA + ko + tg]);
                afh[mt][1] = __float_as_uint(Ah_s[(r0 + 8) * PADA + ko + tg]);
                afh[mt][2] = __float_as_uint(Ah_s[r0 * PADA + ko + tg + 4]);
                afh[mt][3] = __float_as_uint(Ah_s[(r0 + 8) * PADA + ko + tg + 4]);
                afl[mt][0] = __float_as_uint(Al_s[r0 * PADA + ko + tg]);
                afl[mt][1] = __float_as_uint(Al_s[(r0 + 8) * PADA + ko + tg]);
                afl[mt][2] = __float_as_uint(Al_s[r0 * PADA + ko + tg + 4]);
                afl[mt][3] = __float_as_uint(Al_s[(r0 + 8) * PADA + ko + tg + 4]);
            }
#pragma unroll
            for (int nt = 0; nt < 8; nt++) {
                unsigned bh[2], bl[2];
                if (BNT) {
                    int nr = (wn + nt * 8 + g) * PADA;
                    bh[0] = __float_as_uint(Bh_s[nr + ko + tg]);
                    bh[1] = __float_as_uint(Bh_s[nr + ko + tg + 4]);
                    bl[0] = __float_as_uint(Bl_s[nr + ko + tg]);
                    bl[1] = __float_as_uint(Bl_s[nr + ko + tg + 4]);
                } else {
                    int nc = wn + nt * 8 + g;
                    bh[0] = __float_as_uint(Bh_s[(ko + tg) * PADB + nc]);
                    bh[1] = __float_as_uint(Bh_s[(ko + tg + 4) * PADB + nc]);
                    bl[0] = __float_as_uint(Bl_s[(ko + tg) * PADB + nc]);
                    bl[1] = __float_as_uint(Bl_s[(ko + tg + 4) * PADB + nc]);
                }
#pragma unroll
                for (int mt = 0; mt < 2; mt++) {
                    mma_tf32(acc[mt][nt], afh[mt], bh);   // hi*hi
                    mma_tf32(acc[mt][nt], afh[mt], bl);   // hi*lo
                    mma_tf32(acc[mt][nt], afl[mt], bh);   // lo*hi
                }
            }
        }
        __syncthreads();
    }
#undef LOAD_STAGE

    // epilogue: each thread owns pairs (r, c0..c0+1) and (r+8, c0..c0+1)
#pragma unroll
    for (int mt = 0; mt < 2; mt++) {
        int r0 = row0 + wm + mt * 16 + g;
        int r1 = r0 + 8;
#pragma unroll
        for (int nt = 0; nt < 8; nt++) {
            int c0 = col0 + wn + nt * 8 + tg * 2;
            if (c0 < N) {                        // N is even at all call sites
                float b0 = bias ? bias[c0] : 0.f;
                float b1 = bias ? bias[c0 + 1] : 0.f;
                float2 o0 = make_float2(acc[mt][nt][0] + b0, acc[mt][nt][1] + b1);
                float2 o1 = make_float2(acc[mt][nt][2] + b0, acc[mt][nt][3] + b1);
                *reinterpret_cast<float2*>(&C[(size_t)r0 * N + c0]) = o0;
                *reinterpret_cast<float2*>(&C[(size_t)r1 * N + c0]) = o1;
            }
        }
    }
}

// ====================== split-K reduce =======================================
__global__ void reduce_k(const float* __restrict__ part, float* __restrict__ dst,
                         int z, size_t len)
{
    size_t i = (size_t)blockIdx.x * 256 + threadIdx.x;
    if (i >= len) return;
    float s = 0.f;
    for (int zz = 0; zz < z; zz++) s += part[(size_t)zz * len + i];
    dst[i] = s;
}

// ====================== tf32 split of a plain array ==========================
__global__ void split_pair(const float* __restrict__ src, float* __restrict__ h,
                           float* __restrict__ l, int n)
{
    int i = blockIdx.x * 256 + threadIdx.x;
    if (i >= n) return;
    float hh, ll;
    split2(src[i], hh, ll);
    h[i] = hh; l[i] = ll;
}

// ====================== BatchNorm statistics (deterministic, 2-stage) ========
__global__ void bn_partial(const float* __restrict__ X1,
                           float* __restrict__ psum, float* __restrict__ psq)
{
    int ch = threadIdx.x;
    if (ch >= CC2) return;
    int b = blockIdx.x;
    const float* base = X1 + (size_t)b * 256 * CC2 + ch;
    float s = 0.f, q = 0.f;
    for (int r = 0; r < 256; r++) {
        float v = base[(size_t)r * CC2];
        s += v; q += v * v;
    }
    psum[b * CC2 + ch] = s;
    psq[b * CC2 + ch]  = q;
}

__global__ void bn_final(const float* __restrict__ psum, const float* __restrict__ psq,
                         const float* __restrict__ bns, const float* __restrict__ bnb,
                         float* __restrict__ scl, float* __restrict__ shf)
{
    int ch = threadIdx.x;
    if (ch >= CC2) return;
    float s = 0.f, q = 0.f;
    for (int b = 0; b < 256; b++) { s += psum[b * CC2 + ch]; q += psq[b * CC2 + ch]; }
    float mean = s * (1.f / MROWS);
    float var  = q * (1.f / MROWS) - mean * mean;
    float sc = bns[ch] / sqrtf(var + 1e-5f);
    scl[ch] = sc;
    shf[ch] = bnb[ch] - mean * sc;
}

// ====================== gather (roll -ws/2) + BN affine + tf32 split =========
__global__ void gather_qv(const float* __restrict__ X1,
                          const float* __restrict__ scl, const float* __restrict__ shf,
                          float* __restrict__ Qh, float* __restrict__ Ql,
                          float* __restrict__ Vh, float* __restrict__ Vl,
                          int gbase, int lws, int total)
{
    int idx = blockIdx.x * 256 + threadIdx.x;
    if (idx >= total) return;
    const int ws = 1 << lws;
    const int sh = ws >> 1;
    const int D  = (ws * ws) * 60;
    int n = idx / D;
    int d = idx - n * D;
    int cc = d % 60;
    int t  = d / 60;
    int dw = t & (ws - 1);
    int dh = t >> lws;
    const int lh = 7 - lws;
    int b   = n >> (2 * lh);
    int rem = n & ((1 << (2 * lh)) - 1);
    int hh  = rem >> lh;
    int ww  = rem & ((1 << lh) - 1);
    int r = ((hh << lws) + dh + sh) & 127;
    int s = ((ww << lws) + dw + sh) & 127;
    size_t m = ((size_t)b << 14) + ((size_t)r << 7) + s;
    size_t base = m * CC2 + gbase + cc;
    int chq = gbase + cc, chv = chq + 60;
    float q = X1[base]      * scl[chq] + shf[chq];
    float v = X1[base + 60] * scl[chv] + shf[chv];
    float qh, ql, vh, vl;
    split2(q, qh, ql);
    split2(v, vh, vl);
    Qh[idx] = qh; Ql[idx] = ql;
    Vh[idx] = vh; Vl[idx] = vl;
}

// ====================== scatter (roll +ws/2) + tf32 split ====================
__global__ void scatter_y(const float* __restrict__ Yw,
                          float* __restrict__ Ych, float* __restrict__ Ycl,
                          int g, int lws)
{
    int idx = blockIdx.x * 256 + threadIdx.x;
    if (idx >= MROWS * 60) return;
    int cc = idx % 60;
    int m  = idx / 60;
    int so = m & 127, ro = (m >> 7) & 127, b = m >> 14;
    const int ws = 1 << lws, sh = ws >> 1, lh = 7 - lws;
    int r = (ro - sh) & 127, s = (so - sh) & 127;
    int hh = r >> lws, dh = r & (ws - 1);
    int ww = s >> lws, dw = s & (ws - 1);
    int n = (((b << lh) + hh) << lh) + ww;
    int D = (ws * ws) * 60;
    int d = ((dh << lws) + dw) * 60 + cc;
    float y = Yw[(size_t)n * D + d];
    float yh, yl;
    split2(y, yh, yl);
    size_t o = (size_t)m * CIN + g * 60 + cc;
    Ych[o] = yh; Ycl[o] = yl;
}

// ====================== in-place row softmax + tf32 split output =============
__global__ __launch_bounds__(256) void softmax_rows(float* __restrict__ data,
                                                    float* __restrict__ oh,
                                                    float* __restrict__ ol, int N)
{
    __shared__ float sb[4096];
    __shared__ float red[40];
    const int tid = threadIdx.x;
    float* p = data + (size_t)blockIdx.x * N;
    const size_t rowo = (size_t)blockIdx.x * N;

    float mx = -3.402823466e+38f;
    for (int i = tid; i < N; i += 256) { float v = p[i]; sb[i] = v; mx = fmaxf(mx, v); }
#pragma unroll
    for (int o = 16; o > 0; o >>= 1) mx = fmaxf(mx, __shfl_xor_sync(0xffffffffu, mx, o));
    if ((tid & 31) == 0) red[tid >> 5] = mx;
    __syncthreads();
    if (tid == 0) {
        float m2 = red[0];
        for (int i = 1; i < 8; i++) m2 = fmaxf(m2, red[i]);
        red[32] = m2;
    }
    __syncthreads();
    const float mAll = red[32];

    float sum = 0.f;
    for (int i = tid; i < N; i += 256) { float e = expf(sb[i] - mAll); sb[i] = e; sum += e; }
#pragma unroll
    for (int o = 16; o > 0; o >>= 1) sum += __shfl_xor_sync(0xffffffffu, sum, o);
    __syncthreads();
    if ((tid & 31) == 0) red[tid >> 5] = sum;
    __syncthreads();
    if (tid == 0) {
        float s2 = 0.f;
        for (int i = 0; i < 8; i++) s2 += red[i];
        red[33] = 1.f / s2;
    }
    __syncthreads();
    const float inv = red[33];
    for (int i = tid; i < N; i += 256) {
        float v = sb[i] * inv;
        p[i] = v;
        float vh, vl;
        split2(v, vh, vl);
        oh[rowo + i] = vh;
        ol[rowo + i] = vl;
    }
}

// ====================== host orchestration ===================================
extern "C" void kernel_launch(void* const* d_in, const int* in_sizes, int n_in,
                              void* d_out, int out_size)
{
    const float* in  = (const float*)d_in[0];
    const float* w1  = (const float*)d_in[1];
    const float* b1  = (const float*)d_in[2];
    const float* bns = (const float*)d_in[3];
    const float* bnb = (const float*)d_in[4];
    const float* w2  = (const float*)d_in[5];
    const float* b2  = (const float*)d_in[6];
    float* out = (float*)d_out;

    float *X1, *inh, *inl, *w1h, *w1l, *w2h, *w2l;
    float *Qh, *Ql, *Vh, *Vl, *Yw, *Ych, *Ycl, *ah, *al;
    float *part, *psum, *psq, *scl, *shf;
    cudaGetSymbolAddress((void**)&X1,  g_X1);
    cudaGetSymbolAddress((void**)&inh, g_inh);
    cudaGetSymbolAddress((void**)&inl, g_inl);
    cudaGetSymbolAddress((void**)&w1h, g_w1h);
    cudaGetSymbolAddress((void**)&w1l, g_w1l);
    cudaGetSymbolAddress((void**)&w2h, g_w2h);
    cudaGetSymbolAddress((void**)&w2l, g_w2l);
    cudaGetSymbolAddress((void**)&Qh,  g_Qh);
    cudaGetSymbolAddress((void**)&Ql,  g_Ql);
    cudaGetSymbolAddress((void**)&Vh,  g_Vh);
    cudaGetSymbolAddress((void**)&Vl,  g_Vl);
    cudaGetSymbolAddress((void**)&Yw,  g_Yw);
    cudaGetSymbolAddress((void**)&Ych, g_Ych);
    cudaGetSymbolAddress((void**)&Ycl, g_Ycl);
    cudaGetSymbolAddress((void**)&ah,  g_ah);
    cudaGetSymbolAddress((void**)&al,  g_al);
    cudaGetSymbolAddress((void**)&part, g_part);
    cudaGetSymbolAddress((void**)&psum, g_psum);
    cudaGetSymbolAddress((void**)&psq,  g_psq);
    cudaGetSymbolAddress((void**)&scl,  g_scale);
    cudaGetSymbolAddress((void**)&shf,  g_shift);

    // 0) tf32 splits of conv inputs/weights
    split_pair<<<(MROWS * CIN + 255) / 256, 256>>>(in, inh, inl, MROWS * CIN);
    split_pair<<<(CIN * CC2 + 255) / 256, 256>>>(w1, w1h, w1l, CIN * CC2);
    split_pair<<<(CIN * CIN + 255) / 256, 256>>>(w2, w2h, w2l, CIN * CIN);

    // 1) conv1: X1 = in @ W1 + b1   (65536 x 360, K=180), B is [K][N] (NN)
    gemm_tc<false><<<dim3(3, 512, 1), 256>>>(inh, inl, w1h, w1l, X1,
                                             MROWS, CC2, CIN, CIN, b1);

    // 2) BatchNorm statistics
    bn_partial<<<256, 384>>>(X1, psum, psq);
    bn_final<<<1, 384>>>(psum, psq, bns, bnb, scl, shf);

    // attention output regions inside d_out: [y | a4 | a8 | a16]
    float* attn[3] = { out + 11796480, out + 28573696, out + 29622272 };
    const int lwsv[3] = {2, 3, 4};

    for (int g = 0; g < 3; g++) {
        const int lws = lwsv[g];
        const int ws  = 1 << lws;
        const int Nw  = 4 * (128 / ws) * (128 / ws);   // 4096 / 1024 / 256
        const int D   = ws * ws * 60;                   // 960 / 3840 / 15360

        // 3) gather + BN + split
        gather_qv<<<(NDTOT + 255) / 256, 256>>>(X1, scl, shf, Qh, Ql, Vh, Vl,
                                                g * 120, lws, NDTOT);

        // 4) logits S = Q @ Q^T (NT), split-K on the small grids
        if (g == 0) {
            gemm_tc<true><<<dim3(32, 32, 1), 256>>>(Qh, Ql, Qh, Ql, attn[0],
                                                    4096, 4096, 960, 960, nullptr);
        } else if (g == 1) {
            gemm_tc<true><<<dim3(8, 8, 4), 256>>>(Qh, Ql, Qh, Ql, part,
                                                  1024, 1024, 3840, 960, nullptr);
            reduce_k<<<4096, 256>>>(part, attn[1], 4, (size_t)1024 * 1024);
        } else {
            gemm_tc<true><<<dim3(2, 2, 60), 256>>>(Qh, Ql, Qh, Ql, part,
                                                   256, 256, 15360, 256, nullptr);
            reduce_k<<<256, 256>>>(part, attn[2], 60, (size_t)256 * 256);
        }

        // 5) softmax in place (d_out) + split for the next GEMM
        softmax_rows<<<Nw, 256>>>(attn[g], ah, al, Nw);

        // 6) Yw = attn @ V  (NN: V is [K=Nw][N=D])
        gemm_tc<false><<<dim3((D + 127) / 128, Nw / 128, 1), 256>>>(
            ah, al, Vh, Vl, Yw, Nw, D, Nw, Nw, nullptr);

        // 7) scatter back with roll(+ws/2) + split for conv2
        scatter_y<<<(MROWS * 60 + 255) / 256, 256>>>(Yw, Ych, Ycl, g, lws);
    }

    // 8) conv2: y = Ycat @ W2 + b2 -> front of d_out (NN)
    gemm_tc<false><<<dim3(2, 512, 1), 256>>>(Ych, Ycl, w2h, w2l, out,
                                             MROWS, CIN, CIN, CIN, b2);
}

// round 9
// speedup vs baseline: 1.2477x; 1.0725x over previous
#include <cuda_runtime.h>
#include <math.h>
#include <stdint.h>

#define MROWS 65536          // 4*128*128
#define CIN   180
#define CC2   360
#define KPAD  192            // conv K padded to x16
#define NDTOT 3932160        // Nw*D for every path

// ---------------- scratch (static device globals) ---------------------------
__device__ float g_X1[(size_t)MROWS * CC2];
__device__ float g_inh[(size_t)MROWS * KPAD], g_inl[(size_t)MROWS * KPAD];
__device__ float g_w1h[384 * KPAD], g_w1l[384 * KPAD];     // W1^T frag, rows padded 360->384
__device__ float g_w2h[256 * KPAD], g_w2l[256 * KPAD];     // W2^T frag, rows padded 180->256
__device__ float g_Qh[NDTOT], g_Ql[NDTOT];                 // Q frag [Nw][D]
__device__ float g_Vth[4194304], g_Vtl[4194304];           // V^T frag [Dpad][Nw]
__device__ float g_Yw[NDTOT];
__device__ float g_Ycat[(size_t)MROWS * CIN];
__device__ float g_Ych[(size_t)MROWS * KPAD], g_Ycl[(size_t)MROWS * KPAD];
__device__ float g_ah[(size_t)4096 * 4096], g_al[(size_t)4096 * 4096];  // attn frag
__device__ float g_part[4194304];
__device__ float g_psum[256 * CC2], g_psq[256 * CC2];
__device__ float g_scale[CC2], g_shift[CC2];

union U4 { float4 v; float f[4]; unsigned u[4]; };

// ---------------- helpers ----------------------------------------------------
__device__ __forceinline__ void split2(float x, float& h, float& l) {
    unsigned uh, ul;
    asm("cvt.rna.tf32.f32 %0, %1;" : "=r"(uh) : "f"(x));
    h = __uint_as_float(uh);
    float r = x - h;
    asm("cvt.rna.tf32.f32 %0, %1;" : "=r"(ul) : "f"(r));
    l = __uint_as_float(ul);
}

__device__ __forceinline__ void mma_tf32(float* d, const unsigned* a,
                                         const unsigned* b) {
    asm volatile(
        "mma.sync.aligned.m16n8k8.row.col.f32.tf32.tf32.f32 "
        "{%0,%1,%2,%3}, {%4,%5,%6,%7}, {%8,%9}, {%0,%1,%2,%3};"
        : "+f"(d[0]), "+f"(d[1]), "+f"(d[2]), "+f"(d[3])
        : "r"(a[0]), "r"(a[1]), "r"(a[2]), "r"(a[3]), "r"(b[0]), "r"(b[1]));
}

// ============ NT tensor GEMM (3xTF32) on fragment-layout operands ===========
// Fragment layout: chunk=(row>>3)*K16+(k>>4), 128 floats/chunk,
// in-chunk float4 index = (row&7)*4 + (k&3), f[p] = value at k = 4p + (k&3).
// C[M,N] = A[M,K] * B[N,K]^T (+bias). Tiles 128x128, BK=16, 8 warps.
// Split-K via blockIdx.z (Kc16 chunk-blocks), partials at C + z*M*N.
__global__ __launch_bounds__(256) void gemm_tc(
    const float* __restrict__ Ah, const float* __restrict__ Al,
    const float* __restrict__ Bh, const float* __restrict__ Bl,
    float* __restrict__ C, int M, int N, int K16, int Kc16,
    const float* __restrict__ bias)
{
    __shared__ __align__(16) float As_h[2048], As_l[2048], Bs_h[2048], Bs_l[2048];

    const int tid  = threadIdx.x;
    const int row0 = blockIdx.y * 128;
    const int col0 = blockIdx.x * 128;
    const int kb0  = blockIdx.z * Kc16;
    const int kb1  = kb0 + Kc16;
    if (gridDim.z > 1) C += (size_t)blockIdx.z * M * N;

    const int wid = tid >> 5, lane = tid & 31;
    const int wm3 = (wid & 3) * 4;       // row-chunk base for this warp
    const int wn3 = (wid >> 2) * 8;      // col-chunk base
    const int g   = lane >> 2, tg = lane & 3;

    float acc[2][8][4];
#pragma unroll
    for (int mt = 0; mt < 2; mt++)
#pragma unroll
        for (int nt = 0; nt < 8; nt++)
#pragma unroll
            for (int j = 0; j < 4; j++) acc[mt][nt][j] = 0.f;

    // loader: thread -> chunk jc (0..15), float4 slots f4 and f4+16
    const int jc = tid >> 4, f4 = tid & 15;
    const float* pAh = Ah + ((size_t)((row0 >> 3) + jc) * K16) * 128 + f4 * 4;
    const float* pAl = Al + ((size_t)((row0 >> 3) + jc) * K16) * 128 + f4 * 4;
    const float* pBh = Bh + ((size_t)((col0 >> 3) + jc) * K16) * 128 + f4 * 4;
    const float* pBl = Bl + ((size_t)((col0 >> 3) + jc) * K16) * 128 + f4 * 4;
    const int sidx = jc * 128 + f4 * 4;

    float4 rah0, rah1, ral0, ral1, rbh0, rbh1, rbl0, rbl1;
#define LOADK(KB)                                                             \
    do {                                                                      \
        size_t o = (size_t)(KB) * 128;                                        \
        rah0 = *reinterpret_cast<const float4*>(pAh + o);                     \
        rah1 = *reinterpret_cast<const float4*>(pAh + o + 64);                \
        ral0 = *reinterpret_cast<const float4*>(pAl + o);                     \
        ral1 = *reinterpret_cast<const float4*>(pAl + o + 64);                \
        rbh0 = *reinterpret_cast<const float4*>(pBh + o);                     \
        rbh1 = *reinterpret_cast<const float4*>(pBh + o + 64);                \
        rbl0 = *reinterpret_cast<const float4*>(pBl + o);                     \
        rbl1 = *reinterpret_cast<const float4*>(pBl + o + 64);                \
    } while (0)

    LOADK(kb0);

    for (int kb = kb0; kb < kb1; kb++) {
        *reinterpret_cast<float4*>(&As_h[sidx])      = rah0;
        *reinterpret_cast<float4*>(&As_h[sidx + 64]) = rah1;
        *reinterpret_cast<float4*>(&As_l[sidx])      = ral0;
        *reinterpret_cast<float4*>(&As_l[sidx + 64]) = ral1;
        *reinterpret_cast<float4*>(&Bs_h[sidx])      = rbh0;
        *reinterpret_cast<float4*>(&Bs_h[sidx + 64]) = rbh1;
        *reinterpret_cast<float4*>(&Bs_l[sidx])      = rbl0;
        *reinterpret_cast<float4*>(&Bs_l[sidx + 64]) = rbl1;
        __syncthreads();

        if (kb + 1 < kb1) LOADK(kb + 1);

        U4 fAh[4], fAl[4];
#pragma unroll
        for (int j = 0; j < 4; j++) {
            fAh[j].v = *reinterpret_cast<const float4*>(&As_h[(wm3 + j) * 128 + lane * 4]);
            fAl[j].v = *reinterpret_cast<const float4*>(&As_l[(wm3 + j) * 128 + lane * 4]);
        }
#pragma unroll
        for (int nt = 0; nt < 8; nt++) {
            U4 bh, bl;
            bh.v = *reinterpret_cast<const float4*>(&Bs_h[(wn3 + nt) * 128 + lane * 4]);
            bl.v = *reinterpret_cast<const float4*>(&Bs_l[(wn3 + nt) * 128 + lane * 4]);
#pragma unroll
            for (int kh = 0; kh < 2; kh++) {
                unsigned bhu[2] = { bh.u[2 * kh], bh.u[2 * kh + 1] };
                unsigned blu[2] = { bl.u[2 * kh], bl.u[2 * kh + 1] };
#pragma unroll
                for (int mt = 0; mt < 2; mt++) {
                    unsigned ahu[4] = { fAh[2 * mt].u[2 * kh],     fAh[2 * mt + 1].u[2 * kh],
                                        fAh[2 * mt].u[2 * kh + 1], fAh[2 * mt + 1].u[2 * kh + 1] };
                    unsigned alu[4] = { fAl[2 * mt].u[2 * kh],     fAl[2 * mt + 1].u[2 * kh],
                                        fAl[2 * mt].u[2 * kh + 1], fAl[2 * mt + 1].u[2 * kh + 1] };
                    mma_tf32(acc[mt][nt], ahu, bhu);
                    mma_tf32(acc[mt][nt], ahu, blu);
                    mma_tf32(acc[mt][nt], alu, bhu);
                }
            }
        }
        __syncthreads();
    }
#undef LOADK

    // epilogue (C row-major, guard cols)
#pragma unroll
    for (int mt = 0; mt < 2; mt++) {
        int r0 = row0 + wm3 * 8 + mt * 16 + g;
        int r1 = r0 + 8;
#pragma unroll
        for (int nt = 0; nt < 8; nt++) {
            int c0 = col0 + wn3 * 8 + nt * 8 + tg * 2;
            if (c0 < N) {
                float b0 = bias ? bias[c0] : 0.f;
                float b1 = bias ? bias[c0 + 1] : 0.f;
                float2 o0 = make_float2(acc[mt][nt][0] + b0, acc[mt][nt][1] + b1);
                float2 o1 = make_float2(acc[mt][nt][2] + b0, acc[mt][nt][3] + b1);
                *reinterpret_cast<float2*>(&C[(size_t)r0 * N + c0]) = o0;
                *reinterpret_cast<float2*>(&C[(size_t)r1 * N + c0]) = o1;
            }
        }
    }
}

// ====================== split-K reduce =======================================
__global__ void reduce_k(const float* __restrict__ part, float* __restrict__ dst,
                         int z, size_t len)
{
    size_t i = (size_t)blockIdx.x * 256 + threadIdx.x;
    if (i >= len) return;
    float s = 0.f;
    for (int zz = 0; zz < z; zz++) s += part[(size_t)zz * len + i];
    dst[i] = s;
}

// ====================== row-major [R][Ks] -> fragment split ==================
__global__ void to_frag(const float* __restrict__ src, float* __restrict__ h,
                        float* __restrict__ l, int Ks, int total4)
{
    int t4 = blockIdx.x * 256 + threadIdx.x;
    if (t4 >= total4) return;
    int chunk = t4 >> 5, lane = t4 & 31;
    const int K16 = KPAD / 16;
    int rb = chunk / K16, k16 = chunk - rb * K16;
    int row = rb * 8 + (lane >> 2), c = lane & 3;
    U4 oh, ol;
#pragma unroll
    for (int p = 0; p < 4; p++) {
        int k = k16 * 16 + c + 4 * p;
        float v = (k < Ks) ? src[(size_t)row * Ks + k] : 0.f;
        split2(v, oh.f[p], ol.f[p]);
    }
    reinterpret_cast<float4*>(h)[t4] = oh.v;
    reinterpret_cast<float4*>(l)[t4] = ol.v;
}

// ====================== weight transpose -> fragment split ===================
__global__ void wt_frag(const float* __restrict__ W, float* __restrict__ h,
                        float* __restrict__ l, int Ks, int Ns, int total4)
{
    int t4 = blockIdx.x * 256 + threadIdx.x;
    if (t4 >= total4) return;
    int chunk = t4 >> 5, lane = t4 & 31;
    const int K16 = KPAD / 16;
    int rb = chunk / K16, k16 = chunk - rb * K16;
    int n = rb * 8 + (lane >> 2), c = lane & 3;
    U4 oh, ol;
#pragma unroll
    for (int p = 0; p < 4; p++) {
        int k = k16 * 16 + c + 4 * p;
        float v = (n < Ns && k < Ks) ? W[(size_t)k * Ns + n] : 0.f;
        split2(v, oh.f[p], ol.f[p]);
    }
    reinterpret_cast<float4*>(h)[t4] = oh.v;
    reinterpret_cast<float4*>(l)[t4] = ol.v;
}

// ====================== BatchNorm statistics =================================
__global__ void bn_partial(const float* __restrict__ X1,
                           float* __restrict__ psum, float* __restrict__ psq)
{
    int ch = threadIdx.x;
    if (ch >= CC2) return;
    int b = blockIdx.x;
    const float* base = X1 + (size_t)b * 256 * CC2 + ch;
    float s = 0.f, q = 0.f;
    for (int r = 0; r < 256; r++) { float v = base[(size_t)r * CC2]; s += v; q += v * v; }
    psum[b * CC2 + ch] = s;
    psq[b * CC2 + ch]  = q;
}

__global__ void bn_final(const float* __restrict__ psum, const float* __restrict__ psq,
                         const float* __restrict__ bns, const float* __restrict__ bnb,
                         float* __restrict__ scl, float* __restrict__ shf)
{
    int ch = threadIdx.x;
    if (ch >= CC2) return;
    float s = 0.f, q = 0.f;
    for (int b = 0; b < 256; b++) { s += psum[b * CC2 + ch]; q += psq[b * CC2 + ch]; }
    float mean = s * (1.f / MROWS);
    float var  = q * (1.f / MROWS) - mean * mean;
    float sc = bns[ch] / sqrtf(var + 1e-5f);
    scl[ch] = sc;
    shf[ch] = bnb[ch] - mean * sc;
}

// ====================== window source offset (roll -ws/2) ====================
__device__ __forceinline__ size_t src_off(int n, int d, int lws, int& cc) {
    int ws = 1 << lws, sh = ws >> 1, lh = 7 - lws;
    int t = d / 60; cc = d - t * 60;
    int dw = t & (ws - 1), dh = t >> lws;
    int b = n >> (2 * lh);
    int rem = n & ((1 << (2 * lh)) - 1);
    int hh = rem >> lh, ww = rem & ((1 << lh) - 1);
    int r = ((hh << lws) + dh + sh) & 127;
    int s = ((ww << lws) + dw + sh) & 127;
    return (((size_t)b << 14) + ((size_t)r << 7) + s) * CC2;
}

// ====================== Q gather -> fragment split ([Nw][D]) =================
__global__ void gather_q(const float* __restrict__ X1,
                         const float* __restrict__ scl, const float* __restrict__ shf,
                         float* __restrict__ Qh, float* __restrict__ Ql,
                         int gbase, int lws, int K16, int total4)
{
    int t4 = blockIdx.x * 256 + threadIdx.x;
    if (t4 >= total4) return;
    int chunk = t4 >> 5, lane = t4 & 31;
    int rb = chunk / K16, k16 = chunk - rb * K16;
    int n = rb * 8 + (lane >> 2), c = lane & 3;
    U4 oh, ol;
#pragma unroll
    for (int p = 0; p < 4; p++) {
        int d = k16 * 16 + c + 4 * p;
        int cc;
        size_t off = src_off(n, d, lws, cc);
        int ch = gbase + cc;
        float q = X1[off + ch] * scl[ch] + shf[ch];
        split2(q, oh.f[p], ol.f[p]);
    }
    reinterpret_cast<float4*>(Qh)[t4] = oh.v;
    reinterpret_cast<float4*>(Ql)[t4] = ol.v;
}

// ====================== V^T gather -> fragment split ([Dpad][Nw]) ============
__global__ void gather_vt(const float* __restrict__ X1,
                          const float* __restrict__ scl, const float* __restrict__ shf,
                          float* __restrict__ Vh, float* __restrict__ Vl,
                          int gbase, int lws, int K16v, int D, int total4)
{
    int t4 = blockIdx.x * 256 + threadIdx.x;
    if (t4 >= total4) return;
    int chunk = t4 >> 5, lane = t4 & 31;
    int rb = chunk / K16v, n16 = chunk - rb * K16v;
    int d = rb * 8 + (lane >> 2), c = lane & 3;
    U4 oh, ol;
    if (d < D) {
#pragma unroll
        for (int p = 0; p < 4; p++) {
            int n = n16 * 16 + c + 4 * p;
            int cc;
            size_t off = src_off(n, d, lws, cc);
            int ch = gbase + 60 + cc;
            float v = X1[off + ch] * scl[ch] + shf[ch];
            split2(v, oh.f[p], ol.f[p]);
        }
    } else {
        oh.v = make_float4(0.f, 0.f, 0.f, 0.f);
        ol.v = oh.v;
    }
    reinterpret_cast<float4*>(Vh)[t4] = oh.v;
    reinterpret_cast<float4*>(Vl)[t4] = ol.v;
}

// ====================== scatter (roll +ws/2) to plain Ycat ===================
__global__ void scatter_y(const float* __restrict__ Yw, float* __restrict__ Ycat,
                          int g, int lws)
{
    int idx = blockIdx.x * 256 + threadIdx.x;
    if (idx >= MROWS * 60) return;
    int cc = idx % 60;
    int m  = idx / 60;
    int so = m & 127, ro = (m >> 7) & 127, b = m >> 14;
    const int ws = 1 << lws, sh = ws >> 1, lh = 7 - lws;
    int r = (ro - sh) & 127, s = (so - sh) & 127;
    int hh = r >> lws, dh = r & (ws - 1);
    int ww = s >> lws, dw = s & (ws - 1);
    int n = (((b << lh) + hh) << lh) + ww;
    int D = (ws * ws) * 60;
    int d = ((dh << lws) + dw) * 60 + cc;
    Ycat[(size_t)m * CIN + g * 60 + cc] = Yw[(size_t)n * D + d];
}

// ====================== softmax + fragment-split output ======================
__global__ __launch_bounds__(256) void softmax_rows(float* __restrict__ data,
                                                    float* __restrict__ oh,
                                                    float* __restrict__ ol, int N)
{
    __shared__ float sb[4096];
    __shared__ float red[40];
    const int tid = threadIdx.x;
    const int row = blockIdx.x;
    float* p = data + (size_t)row * N;
    const int K16 = N >> 4;
    const size_t rowc = ((size_t)(row >> 3) * K16) << 7;
    const int laneb = (row & 7) << 4;

    float mx = -3.402823466e+38f;
    for (int i = tid; i < N; i += 256) { float v = p[i]; sb[i] = v; mx = fmaxf(mx, v); }
#pragma unroll
    for (int o = 16; o > 0; o >>= 1) mx = fmaxf(mx, __shfl_xor_sync(0xffffffffu, mx, o));
    if ((tid & 31) == 0) red[tid >> 5] = mx;
    __syncthreads();
    if (tid == 0) {
        float m2 = red[0];
        for (int i = 1; i < 8; i++) m2 = fmaxf(m2, red[i]);
        red[32] = m2;
    }
    __syncthreads();
    const float mAll = red[32];

    float sum = 0.f;
    for (int i = tid; i < N; i += 256) { float e = expf(sb[i] - mAll); sb[i] = e; sum += e; }
#pragma unroll
    for (int o = 16; o > 0; o >>= 1) sum += __shfl_xor_sync(0xffffffffu, sum, o);
    __syncthreads();
    if ((tid & 31) == 0) red[tid >> 5] = sum;
    __syncthreads();
    if (tid == 0) {
        float s2 = 0.f;
        for (int i = 0; i < 8; i++) s2 += red[i];
        red[33] = 1.f / s2;
    }
    __syncthreads();
    const float inv = red[33];
    for (int i = tid; i < N; i += 256) {
        float v = sb[i] * inv;
        p[i] = v;
        float vh, vl;
        split2(v, vh, vl);
        size_t o = rowc + ((size_t)(i >> 4) << 7) + laneb + ((i & 3) << 2) + ((i >> 2) & 3);
        oh[o] = vh;
        ol[o] = vl;
    }
}

// ====================== host orchestration ===================================
extern "C" void kernel_launch(void* const* d_in, const int* in_sizes, int n_in,
                              void* d_out, int out_size)
{
    const float* in  = (const float*)d_in[0];
    const float* w1  = (const float*)d_in[1];
    const float* b1  = (const float*)d_in[2];
    const float* bns = (const float*)d_in[3];
    const float* bnb = (const float*)d_in[4];
    const float* w2  = (const float*)d_in[5];
    const float* b2  = (const float*)d_in[6];
    float* out = (float*)d_out;

    float *X1, *inh, *inl, *w1h, *w1l, *w2h, *w2l;
    float *Qh, *Ql, *Vth, *Vtl, *Yw, *Yc, *Ych, *Ycl, *ah, *al;
    float *part, *psum, *psq, *scl, *shf;
    cudaGetSymbolAddress((void**)&X1,  g_X1);
    cudaGetSymbolAddress((void**)&inh, g_inh);
    cudaGetSymbolAddress((void**)&inl, g_inl);
    cudaGetSymbolAddress((void**)&w1h, g_w1h);
    cudaGetSymbolAddress((void**)&w1l, g_w1l);
    cudaGetSymbolAddress((void**)&w2h, g_w2h);
    cudaGetSymbolAddress((void**)&w2l, g_w2l);
    cudaGetSymbolAddress((void**)&Qh,  g_Qh);
    cudaGetSymbolAddress((void**)&Ql,  g_Ql);
    cudaGetSymbolAddress((void**)&Vth, g_Vth);
    cudaGetSymbolAddress((void**)&Vtl, g_Vtl);
    cudaGetSymbolAddress((void**)&Yw,  g_Yw);
    cudaGetSymbolAddress((void**)&Yc,  g_Ycat);
    cudaGetSymbolAddress((void**)&Ych, g_Ych);
    cudaGetSymbolAddress((void**)&Ycl, g_Ycl);
    cudaGetSymbolAddress((void**)&ah,  g_ah);
    cudaGetSymbolAddress((void**)&al,  g_al);
    cudaGetSymbolAddress((void**)&part, g_part);
    cudaGetSymbolAddress((void**)&psum, g_psum);
    cudaGetSymbolAddress((void**)&psq,  g_psq);
    cudaGetSymbolAddress((void**)&scl,  g_scale);
    cudaGetSymbolAddress((void**)&shf,  g_shift);

    // 0) operand prep: input + weights -> fragment split layouts
    to_frag<<<MROWS * KPAD / 4 / 256, 256>>>(in, inh, inl, CIN, MROWS * KPAD / 4);
    wt_frag<<<(384 * KPAD / 4 + 255) / 256, 256>>>(w1, w1h, w1l, CIN, CC2, 384 * KPAD / 4);
    wt_frag<<<(256 * KPAD / 4 + 255) / 256, 256>>>(w2, w2h, w2l, CIN, CIN, 256 * KPAD / 4);

    // 1) conv1: X1 = in @ W1 + b1 (NT vs W1^T)
    gemm_tc<<<dim3(3, 512, 1), 256>>>(inh, inl, w1h, w1l, X1,
                                      MROWS, CC2, KPAD / 16, KPAD / 16, b1);

    // 2) BatchNorm stats
    bn_partial<<<256, 384>>>(X1, psum, psq);
    bn_final<<<1, 384>>>(psum, psq, bns, bnb, scl, shf);

    float* attn[3] = { out + 11796480, out + 28573696, out + 29622272 };
    const int lwsv[3] = {2, 3, 4};
    const int dpadv[3] = {1024, 3840, 15360};

    for (int g = 0; g < 3; g++) {
        const int lws = lwsv[g];
        const int ws  = 1 << lws;
        const int Nw  = 4 * (128 / ws) * (128 / ws);   // 4096 / 1024 / 256
        const int D   = ws * ws * 60;                   // 960 / 3840 / 15360
        const int Dp  = dpadv[g];
        const int K16d = D / 16, K16n = Nw / 16;

        // 3) gathers (fused BN + tf32 split, fragment layouts)
        gather_q<<<NDTOT / 4 / 256, 256>>>(X1, scl, shf, Qh, Ql,
                                           g * 120, lws, K16d, NDTOT / 4);
        gather_vt<<<Dp * Nw / 4 / 256, 256>>>(X1, scl, shf, Vth, Vtl,
                                              g * 120, lws, K16n, D, Dp * Nw / 4);

        // 4) logits S = Q @ Q^T
        if (g == 0) {
            gemm_tc<<<dim3(32, 32, 1), 256>>>(Qh, Ql, Qh, Ql, attn[0],
                                              4096, 4096, 60, 60, nullptr);
        } else if (g == 1) {
            gemm_tc<<<dim3(8, 8, 4), 256>>>(Qh, Ql, Qh, Ql, part,
                                            1024, 1024, 240, 60, nullptr);
            reduce_k<<<4096, 256>>>(part, attn[1], 4, (size_t)1024 * 1024);
        } else {
            gemm_tc<<<dim3(2, 2, 60), 256>>>(Qh, Ql, Qh, Ql, part,
                                             256, 256, 960, 16, nullptr);
            reduce_k<<<256, 256>>>(part, attn[2], 60, (size_t)256 * 256);
        }

        // 5) softmax in place (d_out) + fragment split
        softmax_rows<<<Nw, 256>>>(attn[g], ah, al, Nw);

        // 6) Yw = attn @ V  (NT vs V^T frag)
        gemm_tc<<<dim3(Dp / 128, Nw / 128, 1), 256>>>(ah, al, Vth, Vtl, Yw,
                                                      Nw, D, K16n, K16n, nullptr);

        // 7) scatter back
        scatter_y<<<(MROWS * 60 + 255) / 256, 256>>>(Yw, Yc, g, lws);
    }

    // 8) conv2
    to_frag<<<MROWS * KPAD / 4 / 256, 256>>>(Yc, Ych, Ycl, CIN, MROWS * KPAD / 4);
    gemm_tc<<<dim3(2, 512, 1), 256>>>(Ych, Ycl, w2h, w2l, out,
                                      MROWS, CIN, KPAD / 16, KPAD / 16, b2);
}